// round 1
// baseline (speedup 1.0000x reference)
#include <cuda_runtime.h>
#include <math.h>

// Allpass biquad over [B, 1, T] fp32, T = 480000.
// Parallelization: constant-matrix linear recurrence -> per-warp chunks with
// one warm-up tile (poles decay 0.414^n), intra-tile Kogge-Stone warp scan.

#define FULL 0xffffffffu
#define R 8                   // samples per lane
#define TILE 256              // 32 lanes * R
#define CHUNK_TILES 25        // 6400 samples per warp-chunk
#define CHUNK (CHUNK_TILES * TILE)
#define T_LEN 480000

struct M2 { float a, b, c, d; };  // [[a,b],[c,d]]

__device__ __forceinline__ M2 mmul(const M2& x, const M2& y) {
    M2 r;
    r.a = x.a * y.a + x.b * y.c;
    r.b = x.a * y.b + x.b * y.d;
    r.c = x.c * y.a + x.d * y.c;
    r.d = x.c * y.b + x.d * y.d;
    return r;
}

__global__ void __launch_bounds__(256)
allpass_biquad_kernel(const float* __restrict__ x, float* __restrict__ y,
                      float b0, float b1, float b2, float a1, float a2,
                      int chunks_per_row, int total_chunks)
{
    const int warp_id = (blockIdx.x * blockDim.x + threadIdx.x) >> 5;
    const int lane = threadIdx.x & 31;
    if (warp_id >= total_chunks) return;

    const int row   = warp_id / chunks_per_row;
    const int chunk = warp_id % chunks_per_row;
    const float* xr = x + (size_t)row * T_LEN;
    float*       yr = y + (size_t)row * T_LEN;
    const int start = chunk * CHUNK;

    // ---- build matrix-power constants (cheap, once per thread) ----
    // M = [[-a1, -a2], [1, 0]]
    M2 Mm; Mm.a = -a1; Mm.b = -a2; Mm.c = 1.0f; Mm.d = 0.0f;

    // row 0 of M^j for j = 1..R  (output correction coefficients)
    float c0[R + 1], c1[R + 1];
    {
        M2 cur = Mm;
        c0[1] = cur.a; c1[1] = cur.b;
        #pragma unroll
        for (int j = 2; j <= R; j++) {
            cur = mmul(cur, Mm);
            c0[j] = cur.a; c1[j] = cur.b;
        }
    }
    // P[s] = M^(R * 2^s), s = 0..4 (scan steps); R32 = M^(32R) (tile carry)
    M2 P[5];
    {
        M2 mr = Mm;
        #pragma unroll
        for (int j = 1; j < R; j++) mr = mmul(mr, Mm);  // M^R
        P[0] = mr;
        #pragma unroll
        for (int s = 1; s < 5; s++) P[s] = mmul(P[s - 1], P[s - 1]);
    }
    M2 R32 = mmul(P[4], P[4]);
    // Q = M^(lane * R): product of P[k] over set bits of lane (powers commute)
    M2 Q; Q.a = 1.0f; Q.b = 0.0f; Q.c = 0.0f; Q.d = 1.0f;
    #pragma unroll
    for (int k = 0; k < 5; k++)
        if (lane & (1 << k)) Q = mmul(P[k], Q);

    // ---- main loop over tiles (t = -1 is the unstored warm-up tile) ----
    float si0 = 0.0f, si1 = 0.0f;   // incoming state (y_{-1}, y_{-2}) of tile
    float cx1 = 0.0f, cx2 = 0.0f;   // x_{-1}, x_{-2} before tile
    const int t_first = (chunk == 0) ? 0 : -1;

    for (int t = t_first; t < CHUNK_TILES; t++) {
        const int gbase = start + t * TILE;
        const int goff  = gbase + lane * R;

        // coalesced load of this lane's 8 samples
        const float4* px = reinterpret_cast<const float4*>(xr + goff);
        float4 xa = px[0];
        float4 xb = px[1];
        float xv0 = xa.x, xv1 = xa.y, xv2 = xa.z, xv3 = xa.w;
        float xv4 = xb.x, xv5 = xb.y, xv6 = xb.z, xv7 = xb.w;

        // x history from neighbor lane (lane 0 uses tile carry)
        float xm1 = __shfl_up_sync(FULL, xv7, 1);
        float xm2 = __shfl_up_sync(FULL, xv6, 1);
        if (lane == 0) { xm1 = cx1; xm2 = cx2; }

        // particular solution: zero incoming state
        float yp[R];
        {
            float py1 = 0.0f, py2 = 0.0f, xp1 = xm1, xp2 = xm2;
            float xs[R] = {xv0, xv1, xv2, xv3, xv4, xv5, xv6, xv7};
            #pragma unroll
            for (int k = 0; k < R; k++) {
                float fir = b0 * xs[k] + b1 * xp1 + b2 * xp2;
                float yn  = fir - a1 * py1 - a2 * py2;
                yp[k] = yn;
                py2 = py1; py1 = yn;
                xp2 = xp1; xp1 = xs[k];
            }
        }
        // F_i = end state of this lane's segment (zero incoming)
        float v0 = yp[R - 1];
        float v1 = yp[R - 2];

        // Kogge-Stone affine scan across lanes with constant M^(dR)
        #pragma unroll
        for (int s = 0; s < 5; s++) {
            const int d = 1 << s;
            float t0 = __shfl_up_sync(FULL, v0, d);
            float t1 = __shfl_up_sync(FULL, v1, d);
            if (lane >= d) {
                v0 += P[s].a * t0 + P[s].b * t1;
                v1 += P[s].c * t0 + P[s].d * t1;
            }
        }

        // incoming state for this lane: sigma_i = v_{i-1} + M^(iR) * s_in
        float vp0 = __shfl_up_sync(FULL, v0, 1);
        float vp1 = __shfl_up_sync(FULL, v1, 1);
        if (lane == 0) { vp0 = 0.0f; vp1 = 0.0f; }
        const float sg0 = vp0 + Q.a * si0 + Q.b * si1;
        const float sg1 = vp1 + Q.c * si0 + Q.d * si1;

        // correct and store (skip warm-up tile)
        if (t >= 0) {
            float o[R];
            #pragma unroll
            for (int k = 0; k < R; k++)
                o[k] = yp[k] + c0[k + 1] * sg0 + c1[k + 1] * sg1;
            float4* py4 = reinterpret_cast<float4*>(yr + goff);
            py4[0] = make_float4(o[0], o[1], o[2], o[3]);
            py4[1] = make_float4(o[4], o[5], o[6], o[7]);
        }

        // carries to next tile
        float bv0 = __shfl_sync(FULL, v0, 31);
        float bv1 = __shfl_sync(FULL, v1, 31);
        float nsi0 = bv0 + R32.a * si0 + R32.b * si1;
        float nsi1 = bv1 + R32.c * si0 + R32.d * si1;
        si0 = nsi0; si1 = nsi1;
        cx1 = __shfl_sync(FULL, xv7, 31);
        cx2 = __shfl_sync(FULL, xv6, 31);
    }
}

extern "C" void kernel_launch(void* const* d_in, const int* in_sizes, int n_in,
                              void* d_out, int out_size)
{
    const float* x = (const float*)d_in[0];
    float* y = (float*)d_out;

    const int total = in_sizes[0];
    const int B = total / T_LEN;   // 64

    // Coefficients in float64 then cast, matching the numpy reference exactly.
    const double w0    = 2.0 * M_PI * 4000.0 / 16000.0;
    const double alpha = sin(w0) / (2.0 * 0.707);
    const double cw0   = cos(w0);
    const double a0d   = 1.0 + alpha;
    const float b0 = (float)((1.0 - alpha) / a0d);
    const float b1 = (float)((-2.0 * cw0) / a0d);
    const float b2 = (float)((1.0 + alpha) / a0d);
    const float a1 = (float)((-2.0 * cw0) / a0d);
    const float a2 = (float)((1.0 - alpha) / a0d);

    const int chunks_per_row = T_LEN / CHUNK;        // 75
    const int total_chunks   = B * chunks_per_row;   // 4800 warps
    const int threads = 256;                          // 8 warps/block
    const int blocks  = (total_chunks * 32 + threads - 1) / threads;

    allpass_biquad_kernel<<<blocks, threads>>>(x, y, b0, b1, b2, a1, a2,
                                               chunks_per_row, total_chunks);
}

// round 2
// speedup vs baseline: 1.0420x; 1.0420x over previous
#include <cuda_runtime.h>
#include <math.h>

// Allpass biquad over [B, 1, T] fp32, T = 480000.
// Warp-per-chunk blocked scan:
//   - each warp owns a 1280-sample chunk (5 tiles of 256)
//   - 32-sample serial warm-up establishes incoming state (poles decay 0.414^n,
//     so truncation error ~6e-13)
//   - per tile: 8 samples/lane particular solution, 5-step Kogge-Stone affine
//     scan with constant matrices, 2-FMA/sample correction
// All scan-matrix constants are precomputed on the host and passed via kernel
// params (constant bank) to keep per-thread register count low.

#define FULL 0xffffffffu
#define R 8                   // samples per lane
#define TILE 256              // 32 lanes * R
#define CHUNK_TILES 5         // 1280 samples per warp-chunk
#define CHUNK (CHUNK_TILES * TILE)
#define T_LEN 480000
#define WARMUP 32

struct KParams {
    float b0, b1, b2, a1, a2;
    float P[5][4];     // M^(R*2^s), row-major 2x2
    float R32m[4];     // M^(32R)
    float c0[R], c1[R];  // row 0 of M^(k+1), k=0..R-1
    float Q[32][4];    // M^(lane*R)
};

__global__ void __launch_bounds__(256)
allpass_biquad_kernel(const float* __restrict__ x, float* __restrict__ y,
                      const KParams p, int chunks_per_row, int total_chunks)
{
    const int warp_id = (blockIdx.x * blockDim.x + threadIdx.x) >> 5;
    const int lane = threadIdx.x & 31;
    if (warp_id >= total_chunks) return;

    const int row   = warp_id / chunks_per_row;
    const int chunk = warp_id % chunks_per_row;
    const float* xr = x + (size_t)row * T_LEN;
    float*       yr = y + (size_t)row * T_LEN;
    const int start = chunk * CHUNK;

    const float b0 = p.b0, b1 = p.b1, b2 = p.b2, a1 = p.a1, a2 = p.a2;

    // per-lane Q = M^(lane*R)
    const float q00 = p.Q[lane][0], q01 = p.Q[lane][1];
    const float q10 = p.Q[lane][2], q11 = p.Q[lane][3];

    // ---- warm-up: 32 serial samples (redundant on all lanes) ----
    float si0 = 0.0f, si1 = 0.0f;   // incoming y-state (y_{-1}, y_{-2})
    float cx1 = 0.0f, cx2 = 0.0f;   // x_{-1}, x_{-2}
    if (chunk != 0) {
        const float xw = xr[start - WARMUP + lane];  // one coalesced 128B line
        float py1 = 0.0f, py2 = 0.0f, xp1 = 0.0f, xp2 = 0.0f;
        #pragma unroll
        for (int k = 0; k < WARMUP; k++) {
            const float xk = __shfl_sync(FULL, xw, k);
            const float yn = b0 * xk + b1 * xp1 + b2 * xp2 - a1 * py1 - a2 * py2;
            py2 = py1; py1 = yn;
            xp2 = xp1; xp1 = xk;
        }
        si0 = py1; si1 = py2; cx1 = xp1; cx2 = xp2;
    }

    // ---- 5 tiles, fully unrolled so tile loads can be front-issued ----
    #pragma unroll
    for (int t = 0; t < CHUNK_TILES; t++) {
        const int goff = start + t * TILE + lane * R;

        const float4* px = reinterpret_cast<const float4*>(xr + goff);
        const float4 xa = __ldcs(px + 0);
        const float4 xb = __ldcs(px + 1);
        const float xs[R] = {xa.x, xa.y, xa.z, xa.w, xb.x, xb.y, xb.z, xb.w};

        // x history from neighbor lane (lane 0 uses chunk/tile carry)
        float xm1 = __shfl_up_sync(FULL, xs[7], 1);
        float xm2 = __shfl_up_sync(FULL, xs[6], 1);
        if (lane == 0) { xm1 = cx1; xm2 = cx2; }

        // particular solution with zero incoming y-state
        float yp[R];
        {
            float py1 = 0.0f, py2 = 0.0f, xp1 = xm1, xp2 = xm2;
            #pragma unroll
            for (int k = 0; k < R; k++) {
                const float fir = b0 * xs[k] + b1 * xp1 + b2 * xp2;
                const float yn  = fir - a1 * py1 - a2 * py2;
                yp[k] = yn;
                py2 = py1; py1 = yn;
                xp2 = xp1; xp1 = xs[k];
            }
        }

        // Kogge-Stone affine scan of segment end-states across lanes
        float v0 = yp[R - 1];
        float v1 = yp[R - 2];
        #pragma unroll
        for (int s = 0; s < 5; s++) {
            const int d = 1 << s;
            const float t0 = __shfl_up_sync(FULL, v0, d);
            const float t1 = __shfl_up_sync(FULL, v1, d);
            if (lane >= d) {
                v0 += p.P[s][0] * t0 + p.P[s][1] * t1;
                v1 += p.P[s][2] * t0 + p.P[s][3] * t1;
            }
        }

        // incoming state for this lane: sigma = v_{lane-1} + Q * s_in
        float vp0 = __shfl_up_sync(FULL, v0, 1);
        float vp1 = __shfl_up_sync(FULL, v1, 1);
        if (lane == 0) { vp0 = 0.0f; vp1 = 0.0f; }
        const float sg0 = vp0 + q00 * si0 + q01 * si1;
        const float sg1 = vp1 + q10 * si0 + q11 * si1;

        // correct and store (streaming)
        float4 o0, o1;
        o0.x = yp[0] + p.c0[0] * sg0 + p.c1[0] * sg1;
        o0.y = yp[1] + p.c0[1] * sg0 + p.c1[1] * sg1;
        o0.z = yp[2] + p.c0[2] * sg0 + p.c1[2] * sg1;
        o0.w = yp[3] + p.c0[3] * sg0 + p.c1[3] * sg1;
        o1.x = yp[4] + p.c0[4] * sg0 + p.c1[4] * sg1;
        o1.y = yp[5] + p.c0[5] * sg0 + p.c1[5] * sg1;
        o1.z = yp[6] + p.c0[6] * sg0 + p.c1[6] * sg1;
        o1.w = yp[7] + p.c0[7] * sg0 + p.c1[7] * sg1;
        float4* py4 = reinterpret_cast<float4*>(yr + goff);
        __stcs(py4 + 0, o0);
        __stcs(py4 + 1, o1);

        // carries to next tile
        const float bv0 = __shfl_sync(FULL, v0, 31);
        const float bv1 = __shfl_sync(FULL, v1, 31);
        const float nsi0 = bv0 + p.R32m[0] * si0 + p.R32m[1] * si1;
        const float nsi1 = bv1 + p.R32m[2] * si0 + p.R32m[3] * si1;
        si0 = nsi0; si1 = nsi1;
        cx1 = __shfl_sync(FULL, xs[7], 31);
        cx2 = __shfl_sync(FULL, xs[6], 31);
    }
}

// host-side 2x2 (double precision) helpers
struct M2d { double a, b, c, d; };
static inline M2d mmul_h(const M2d& x, const M2d& y) {
    return { x.a * y.a + x.b * y.c, x.a * y.b + x.b * y.d,
             x.c * y.a + x.d * y.c, x.c * y.b + x.d * y.d };
}

extern "C" void kernel_launch(void* const* d_in, const int* in_sizes, int n_in,
                              void* d_out, int out_size)
{
    const float* x = (const float*)d_in[0];
    float* y = (float*)d_out;

    const int total = in_sizes[0];
    const int B = total / T_LEN;   // 64

    // Coefficients in float64 then cast, matching the numpy reference.
    const double w0    = 2.0 * M_PI * 4000.0 / 16000.0;
    const double alpha = sin(w0) / (2.0 * 0.707);
    const double cw0   = cos(w0);
    const double a0d   = 1.0 + alpha;
    KParams p;
    p.b0 = (float)((1.0 - alpha) / a0d);
    p.b1 = (float)((-2.0 * cw0) / a0d);
    p.b2 = (float)((1.0 + alpha) / a0d);
    p.a1 = (float)((-2.0 * cw0) / a0d);
    p.a2 = (float)((1.0 - alpha) / a0d);

    // transition matrix M = [[-a1, -a2], [1, 0]] (use float-cast coeffs so the
    // decomposition matches the device recurrence as closely as possible)
    M2d M = { -(double)p.a1, -(double)p.a2, 1.0, 0.0 };

    // c0/c1: row 0 of M^(k+1), k = 0..R-1
    {
        M2d cur = M;
        p.c0[0] = (float)cur.a; p.c1[0] = (float)cur.b;
        for (int k = 1; k < R; k++) {
            cur = mmul_h(cur, M);
            p.c0[k] = (float)cur.a; p.c1[k] = (float)cur.b;
        }
    }
    // P[s] = M^(R*2^s); R32 = M^(32R)
    M2d Pd[5];
    {
        M2d mr = M;
        for (int j = 1; j < R; j++) mr = mmul_h(mr, M);
        Pd[0] = mr;
        for (int s = 1; s < 5; s++) Pd[s] = mmul_h(Pd[s - 1], Pd[s - 1]);
        for (int s = 0; s < 5; s++) {
            p.P[s][0] = (float)Pd[s].a; p.P[s][1] = (float)Pd[s].b;
            p.P[s][2] = (float)Pd[s].c; p.P[s][3] = (float)Pd[s].d;
        }
        M2d r32 = mmul_h(Pd[4], Pd[4]);
        p.R32m[0] = (float)r32.a; p.R32m[1] = (float)r32.b;
        p.R32m[2] = (float)r32.c; p.R32m[3] = (float)r32.d;
    }
    // Q[lane] = M^(lane*R)
    {
        M2d q = { 1.0, 0.0, 0.0, 1.0 };
        for (int lane = 0; lane < 32; lane++) {
            p.Q[lane][0] = (float)q.a; p.Q[lane][1] = (float)q.b;
            p.Q[lane][2] = (float)q.c; p.Q[lane][3] = (float)q.d;
            q = mmul_h(Pd[0], q);  // multiply by M^R
        }
    }

    const int chunks_per_row = T_LEN / CHUNK;        // 375
    const int total_chunks   = B * chunks_per_row;   // 24000 warps
    const int threads = 256;
    const int blocks  = (total_chunks * 32 + threads - 1) / threads;

    allpass_biquad_kernel<<<blocks, threads>>>(x, y, p, chunks_per_row,
                                               total_chunks);
}